// round 1
// baseline (speedup 1.0000x reference)
#include <cuda_runtime.h>
#include <cuda_bf16.h>
#include <math.h>

// Problem constants
#define BB    16384
#define HH    32
#define KVH   8
#define DD    128
#define RBIT  128
#define HID   4096      // H*D
#define KOUT  1024      // KVH*D

// Scratch (device globals; no allocations allowed)
__device__ float g_Q[(size_t)BB * HID];   // 256 MB
__device__ float g_K[(size_t)BB * KOUT];  // 64 MB

// ---------------------------------------------------------------------------
// packed f32x2 helpers (ptxas never auto-fuses; see SASS_QUICKREF patterns)
// ---------------------------------------------------------------------------
__device__ __forceinline__ unsigned long long pack2(float x, float y) {
    unsigned long long r;
    asm("mov.b64 %0, {%1,%2};" : "=l"(r) : "f"(x), "f"(y));
    return r;
}
__device__ __forceinline__ void ffma2(unsigned long long& c,
                                      unsigned long long a,
                                      unsigned long long b) {
    asm("fma.rn.f32x2 %0, %1, %2, %0;" : "+l"(c) : "l"(a), "l"(b));
}
__device__ __forceinline__ float2 unpack2(unsigned long long v) {
    float2 r;
    asm("mov.b64 {%0,%1}, %2;" : "=f"(r.x), "=f"(r.y) : "l"(v));
    return r;
}

// ---------------------------------------------------------------------------
// Tiled fp32 GEMM: C[M,N] = A[M,K] @ W[K,N] + bias[N]
// BM=BN=128, BK=16, 256 threads, 8x8 per-thread microtile (as 8x4 f32x2)
// M,N,K all divisible by tile sizes for this problem (16384, 4096/1024, 4096)
// ---------------------------------------------------------------------------
#define BM 128
#define BN 128
#define BK 16

__global__ __launch_bounds__(256) void gemm_bias_kernel(
    const float* __restrict__ A, const float* __restrict__ W,
    const float* __restrict__ bias, float* __restrict__ C,
    int M, int N, int K)
{
    __shared__ float As[BK][BM];
    __shared__ float Ws[BK][BN];

    const int bm = blockIdx.y * BM;
    const int bn = blockIdx.x * BN;
    const int tid = threadIdx.x;
    const int tr = tid >> 4;   // 0..15
    const int tc = tid & 15;   // 0..15

    unsigned long long acc[8][4];
    #pragma unroll
    for (int i = 0; i < 8; i++)
        #pragma unroll
        for (int j = 0; j < 4; j++) acc[i][j] = 0ULL;

    const float* Ab = A + (size_t)bm * K;

    for (int k0 = 0; k0 < K; k0 += BK) {
        // Load A tile (BM x BK) -> As transposed [k][m]
        #pragma unroll
        for (int t = 0; t < 2; t++) {
            int idx = tid + t * 256;          // float4 index, 0..511
            int row = idx >> 2;               // 0..127
            int c4  = idx & 3;                // 0..3
            float4 v = *reinterpret_cast<const float4*>(
                &Ab[(size_t)row * K + k0 + c4 * 4]);
            As[c4 * 4 + 0][row] = v.x;
            As[c4 * 4 + 1][row] = v.y;
            As[c4 * 4 + 2][row] = v.z;
            As[c4 * 4 + 3][row] = v.w;
        }
        // Load W tile (BK x BN) row-major
        #pragma unroll
        for (int t = 0; t < 2; t++) {
            int idx = tid + t * 256;          // float4 index, 0..511
            int row = idx >> 5;               // 0..15
            int c4  = idx & 31;               // 0..31
            *reinterpret_cast<float4*>(&Ws[row][c4 * 4]) =
                *reinterpret_cast<const float4*>(
                    &W[(size_t)(k0 + row) * N + bn + c4 * 4]);
        }
        __syncthreads();

        #pragma unroll
        for (int k = 0; k < BK; k++) {
            float4 a0 = *reinterpret_cast<const float4*>(&As[k][tr * 8]);
            float4 a1 = *reinterpret_cast<const float4*>(&As[k][tr * 8 + 4]);
            float4 b0 = *reinterpret_cast<const float4*>(&Ws[k][tc * 8]);
            float4 b1 = *reinterpret_cast<const float4*>(&Ws[k][tc * 8 + 4]);
            float ra[8] = {a0.x, a0.y, a0.z, a0.w, a1.x, a1.y, a1.z, a1.w};
            unsigned long long rb[4] = {
                pack2(b0.x, b0.y), pack2(b0.z, b0.w),
                pack2(b1.x, b1.y), pack2(b1.z, b1.w)};
            #pragma unroll
            for (int i = 0; i < 8; i++) {
                unsigned long long a2 = pack2(ra[i], ra[i]);
                #pragma unroll
                for (int j = 0; j < 4; j++) ffma2(acc[i][j], a2, rb[j]);
            }
        }
        __syncthreads();
    }

    // Epilogue: + bias, vectorized stores
    const int colb = bn + tc * 8;
    float4 bia0 = *reinterpret_cast<const float4*>(&bias[colb]);
    float4 bia1 = *reinterpret_cast<const float4*>(&bias[colb + 4]);
    #pragma unroll
    for (int i = 0; i < 8; i++) {
        int row = bm + tr * 8 + i;
        float2 c0 = unpack2(acc[i][0]);
        float2 c1 = unpack2(acc[i][1]);
        float2 c2 = unpack2(acc[i][2]);
        float2 c3 = unpack2(acc[i][3]);
        float4 o0 = make_float4(c0.x + bia0.x, c0.y + bia0.y,
                                c1.x + bia0.z, c1.y + bia0.w);
        float4 o1 = make_float4(c2.x + bia1.x, c2.y + bia1.y,
                                c3.x + bia1.z, c3.y + bia1.w);
        *reinterpret_cast<float4*>(&C[(size_t)row * N + colb])     = o0;
        *reinterpret_cast<float4*>(&C[(size_t)row * N + colb + 4]) = o1;
    }
}

// ---------------------------------------------------------------------------
// Fused tail: one block (128 threads) per (b, kvh). Computes k-hash once,
// reuses across the G=4 grouped query heads.
// out[0 : B*H)        = attn_weights
// out[B*H : 2*B*H)    = ham_weights
// ---------------------------------------------------------------------------
__global__ __launch_bounds__(128) void fused_tail_kernel(
    const float* __restrict__ Q, const float* __restrict__ Kp,
    const float* __restrict__ hw, float* __restrict__ out)
{
    const int blk = blockIdx.x;      // b*KVH + kvh
    const int b   = blk >> 3;
    const int kvh = blk & 7;
    const int j   = threadIdx.x;     // 0..127 (dim / rbit index)

    __shared__ float sq[4][128];
    __shared__ float sk[128];
    __shared__ float racc[13][4];

    const float kv = Kp[(size_t)b * KOUT + kvh * DD + j];
    sk[j] = kv;
    float qv[4];
    #pragma unroll
    for (int g = 0; g < 4; g++) {
        qv[g] = Q[(size_t)b * HID + (kvh * 4 + g) * DD + j];
        sq[g][j] = qv[g];
    }
    __syncthreads();

    float vals[13];
    vals[0] = kv * kv;                           // k_norm^2 partial
    #pragma unroll
    for (int g = 0; g < 4; g++) {
        vals[1 + g] = qv[g] * kv;                // dot partial
        vals[5 + g] = qv[g] * qv[g];             // q_norm^2 partial
    }

    // Hash projections: column j of (x @ hash_w); hash_w reads coalesced.
    float qc[4] = {0.f, 0.f, 0.f, 0.f};
    float kc = 0.f;
    #pragma unroll 4
    for (int d = 0; d < 128; d++) {
        float w  = __ldg(&hw[d * RBIT + j]);
        kc += sk[d] * w;
        #pragma unroll
        for (int g = 0; g < 4; g++) qc[g] += sq[g][d] * w;
    }
    const float kcb = 0.5f * (tanhf(kc) + 1.0f);
    #pragma unroll
    for (int g = 0; g < 4; g++) {
        float qcb = 0.5f * (tanhf(qc[g]) + 1.0f);
        vals[9 + g] = fabsf(qcb - kcb);          // ham partial
    }

    // Block-reduce 13 scalars
    const int lane = j & 31, warp = j >> 5;
    #pragma unroll
    for (int s = 0; s < 13; s++) {
        float v = vals[s];
        #pragma unroll
        for (int o = 16; o > 0; o >>= 1) v += __shfl_down_sync(0xffffffffu, v, o);
        if (lane == 0) racc[s][warp] = v;
    }
    __syncthreads();
    if (j < 13)
        racc[j][0] = racc[j][0] + racc[j][1] + racc[j][2] + racc[j][3];
    __syncthreads();

    if (j < 4) {
        const float inv = 0.08838834764831845f;  // 1/sqrt(128)
        const int g = j;
        const int h = kvh * 4 + g;
        const size_t oidx = (size_t)b * HH + h;
        const float dot = racc[1 + g][0];
        const float qn  = sqrtf(racc[5 + g][0]);
        const float kn  = sqrtf(racc[0][0]);
        const float ham = racc[9 + g][0];
        out[oidx] = dot * inv;
        out[(size_t)BB * HH + oidx] =
            (1.0f - 2.0f * ham / (float)RBIT) * qn * kn * inv;
    }
}

// ---------------------------------------------------------------------------
extern "C" void kernel_launch(void* const* d_in, const int* in_sizes, int n_in,
                              void* d_out, int out_size)
{
    const float* q_hidden = (const float*)d_in[0];
    const float* k_hidden = (const float*)d_in[1];
    const float* q_w      = (const float*)d_in[2];
    const float* q_b      = (const float*)d_in[3];
    const float* k_w      = (const float*)d_in[4];
    const float* k_b      = (const float*)d_in[5];
    const float* hash_w   = (const float*)d_in[6];
    float* out = (float*)d_out;

    void* qp = nullptr;
    void* kp = nullptr;
    cudaGetSymbolAddress(&qp, g_Q);
    cudaGetSymbolAddress(&kp, g_K);
    float* Qbuf = (float*)qp;
    float* Kbuf = (float*)kp;

    // Q projection: [B, HID] = q_hidden @ q_w + q_b
    gemm_bias_kernel<<<dim3(HID / BN, BB / BM), 256>>>(
        q_hidden, q_w, q_b, Qbuf, BB, HID, HID);
    // K projection: [B, KOUT] = k_hidden @ k_w + k_b
    gemm_bias_kernel<<<dim3(KOUT / BN, BB / BM), 256>>>(
        k_hidden, k_w, k_b, Kbuf, BB, KOUT, HID);
    // Fused scores + hash tail
    fused_tail_kernel<<<BB * KVH, 128>>>(Qbuf, Kbuf, hash_w, out);
}